// round 1
// baseline (speedup 1.0000x reference)
#include <cuda_runtime.h>
#include <cuda_bf16.h>

// Problem constants
#define BB 4
#define HH 16
#define LL 8192
#define DD 64
#define BH (BB*HH)            // 64
#define NPOS (BH*LL)          // 524288

// Kernel-1 tiling
#define TS 64                 // positions per block
#define KK 128                // reduction dim (q:64 + k:64)
#define WST 68                // padded row stride for Ws (floats), mult of 4

// Scratch (no cudaMalloc allowed)
__device__ float g_w[NPOS];
__device__ float g_rsum[BH];

__device__ __forceinline__ float tanh_fast(float x) {
    float xc = fminf(fmaxf(x, -15.f), 15.f);
    float z = __expf(2.f * xc);
    return (z - 1.f) / (z + 1.f);
}

// ---------------------------------------------------------------------------
// Kernel 1: per-position e = va . tanh(Wa q + Ua k + b), w = mask ? exp(e) : 0
// Tile: 64 positions x 64 out-dims, K=128. 128 threads, each 8 pos x 4 dims.
// ---------------------------------------------------------------------------
__global__ __launch_bounds__(128) void attn_logits_kernel(
    const float* __restrict__ q, const float* __restrict__ k,
    const int* __restrict__ mask,
    const float* __restrict__ Wa_w, const float* __restrict__ Wa_b,
    const float* __restrict__ Ua_w, const float* __restrict__ Ua_b,
    const float* __restrict__ va_w, const float* __restrict__ va_b)
{
    extern __shared__ float sm[];
    float* Ws   = sm;                      // [KK][WST]  weights, Ws[kk][d]
    float* Xs   = Ws + KK * WST;           // [KK][TS]   inputs,  Xs[kk][pos]
    float* bias = Xs + KK * TS;            // [64]
    float* vas  = bias + DD;               // [64]

    const int t = threadIdx.x;             // 0..127
    const int pos0 = blockIdx.x * TS;      // global flat position base

    // ---- load weights transposed into shared: Ws[kk][d] = W[d][kk] ----
    {
        int d  = t & 63;
        int kh = t >> 6;                   // 0 or 1 -> k-range halves
        const float4* wa4 = (const float4*)(Wa_w + d * DD + 32 * kh);
        const float4* ua4 = (const float4*)(Ua_w + d * DD + 32 * kh);
        #pragma unroll
        for (int i = 0; i < 8; i++) {
            float4 a = wa4[i];
            float4 u = ua4[i];
            int kk = 32 * kh + 4 * i;
            Ws[(kk + 0) * WST + d] = a.x;
            Ws[(kk + 1) * WST + d] = a.y;
            Ws[(kk + 2) * WST + d] = a.z;
            Ws[(kk + 3) * WST + d] = a.w;
            Ws[(kk + 64) * WST + d] = u.x;
            Ws[(kk + 65) * WST + d] = u.y;
            Ws[(kk + 66) * WST + d] = u.z;
            Ws[(kk + 67) * WST + d] = u.w;
        }
        if (t < 64) {
            bias[t] = Wa_b[t] + Ua_b[t];
            vas[t]  = va_w[t];
        }
    }

    // ---- load x tile transposed: Xs[kk][p] (kk<64 -> q, kk>=64 -> k) ----
    {
        int p    = t & 63;
        int half = t >> 6;
        const float4* q4 = (const float4*)(q + (size_t)(pos0 + p) * DD + 32 * half);
        const float4* k4 = (const float4*)(k + (size_t)(pos0 + p) * DD + 32 * half);
        #pragma unroll
        for (int i = 0; i < 8; i++) {
            float4 a = q4[i];
            float4 b = k4[i];
            int kk = 32 * half + 4 * i;
            Xs[(kk + 0) * TS + p] = a.x;
            Xs[(kk + 1) * TS + p] = a.y;
            Xs[(kk + 2) * TS + p] = a.z;
            Xs[(kk + 3) * TS + p] = a.w;
            Xs[(kk + 64) * TS + p] = b.x;
            Xs[(kk + 65) * TS + p] = b.y;
            Xs[(kk + 66) * TS + p] = b.z;
            Xs[(kk + 67) * TS + p] = b.w;
        }
    }
    __syncthreads();

    const int tx = t & 15;   // dim group: dims 4*tx .. 4*tx+3
    const int ty = t >> 4;   // pos group: pos  8*ty .. 8*ty+7

    float acc[8][4];
    #pragma unroll
    for (int i = 0; i < 8; i++)
        #pragma unroll
        for (int j = 0; j < 4; j++) acc[i][j] = 0.f;

    #pragma unroll 16
    for (int kk = 0; kk < KK; kk++) {
        float4 w  = *(const float4*)&Ws[kk * WST + 4 * tx];
        float4 xa = *(const float4*)&Xs[kk * TS + 8 * ty];
        float4 xb = *(const float4*)&Xs[kk * TS + 8 * ty + 4];
        float xs[8] = {xa.x, xa.y, xa.z, xa.w, xb.x, xb.y, xb.z, xb.w};
        #pragma unroll
        for (int i = 0; i < 8; i++) {
            acc[i][0] = fmaf(xs[i], w.x, acc[i][0]);
            acc[i][1] = fmaf(xs[i], w.y, acc[i][1]);
            acc[i][2] = fmaf(xs[i], w.z, acc[i][2]);
            acc[i][3] = fmaf(xs[i], w.w, acc[i][3]);
        }
    }

    // ---- epilogue: tanh, va-dot, 16-lane reduce, masked exp ----
    float b0 = bias[4 * tx + 0], b1 = bias[4 * tx + 1];
    float b2 = bias[4 * tx + 2], b3 = bias[4 * tx + 3];
    float v0 = vas[4 * tx + 0], v1 = vas[4 * tx + 1];
    float v2 = vas[4 * tx + 2], v3 = vas[4 * tx + 3];
    float vb = va_b[0];

    float ep[8];
    #pragma unroll
    for (int i = 0; i < 8; i++) {
        float s;
        s  = v0 * tanh_fast(acc[i][0] + b0);
        s += v1 * tanh_fast(acc[i][1] + b1);
        s += v2 * tanh_fast(acc[i][2] + b2);
        s += v3 * tanh_fast(acc[i][3] + b3);
        #pragma unroll
        for (int m = 8; m >= 1; m >>= 1)
            s += __shfl_xor_sync(0xffffffffu, s, m, 16);
        ep[i] = s;
    }

    if (tx == 0) {
        #pragma unroll
        for (int i = 0; i < 8; i++) {
            int pos = pos0 + 8 * ty + i;
            float e = ep[i] + vb;
            float w = (mask[pos] != 0) ? __expf(e) : 0.f;
            g_w[pos] = w;
        }
    }
}

// ---------------------------------------------------------------------------
// Kernel 2: per-(b,h) sum of w over L, store reciprocal. Deterministic.
// ---------------------------------------------------------------------------
__global__ __launch_bounds__(256) void row_sum_kernel()
{
    __shared__ float red[256];
    int bh = blockIdx.x;
    int t = threadIdx.x;
    float s = 0.f;
    const float* wrow = g_w + (size_t)bh * LL;
    for (int l = t; l < LL; l += 256) s += wrow[l];
    red[t] = s;
    __syncthreads();
    for (int m = 128; m > 0; m >>= 1) {
        if (t < m) red[t] += red[t + m];
        __syncthreads();
    }
    if (t == 0) g_rsum[bh] = 1.f / red[0];
}

// ---------------------------------------------------------------------------
// Kernel 3: out = alpha * v  (float4)
// ---------------------------------------------------------------------------
__global__ __launch_bounds__(1024) void scale_v_kernel(
    const float* __restrict__ v, float* __restrict__ out)
{
    int i4 = blockIdx.x * 1024 + threadIdx.x;   // 8192 blocks * 1024 = N/4 exactly
    int pos = i4 >> 4;                           // 16 float4 per position
    int bh  = pos >> 13;                         // / 8192
    float w = g_w[pos] * g_rsum[bh];
    float4 vv = ((const float4*)v)[i4];
    vv.x *= w; vv.y *= w; vv.z *= w; vv.w *= w;
    ((float4*)out)[i4] = vv;
}

extern "C" void kernel_launch(void* const* d_in, const int* in_sizes, int n_in,
                              void* d_out, int out_size)
{
    const float* q    = (const float*)d_in[0];
    const float* k    = (const float*)d_in[1];
    const float* v    = (const float*)d_in[2];
    const int*   mask = (const int*)d_in[3];
    const float* Wa_w = (const float*)d_in[4];
    const float* Wa_b = (const float*)d_in[5];
    const float* Ua_w = (const float*)d_in[6];
    const float* Ua_b = (const float*)d_in[7];
    const float* va_w = (const float*)d_in[8];
    const float* va_b = (const float*)d_in[9];
    float* out = (float*)d_out;

    const int smem1 = (KK * WST + KK * TS + 2 * DD) * (int)sizeof(float); // 68096 B
    cudaFuncSetAttribute(attn_logits_kernel,
                         cudaFuncAttributeMaxDynamicSharedMemorySize, smem1);

    attn_logits_kernel<<<NPOS / TS, 128, smem1>>>(q, k, mask, Wa_w, Wa_b,
                                                  Ua_w, Ua_b, va_w, va_b);
    row_sum_kernel<<<BH, 256>>>();
    scale_v_kernel<<<(NPOS * DD / 4) / 1024, 1024>>>(v, out);
}

// round 2
// speedup vs baseline: 1.2445x; 1.2445x over previous
#include <cuda_runtime.h>
#include <cuda_bf16.h>

// Problem constants
#define BB 4
#define HH 16
#define LL 8192
#define DD 64
#define BH (BB*HH)            // 64
#define NPOS (BH*LL)          // 524288

// Kernel-1 tiling
#define TS 64                 // positions per block
#define KH 64                 // k-steps per phase (q-phase, k-phase)
#define WST 68                // padded row stride for Ws (floats), mult of 4

// Scratch (no cudaMalloc allowed)
__device__ float g_w[NPOS];
__device__ float g_rsum[BH];

__device__ __forceinline__ float tanh_fast(float x) {
    float xc = fminf(fmaxf(x, -15.f), 15.f);
    float z = __expf(2.f * xc);
    return (z - 1.f) / (z + 1.f);
}

#define FMA_F32X2(acc, x2, w2) \
    asm("fma.rn.f32x2 %0, %1, %2, %0;" : "+l"(acc) : "l"(x2), "l"(w2))

#define PACK_BCAST(out, f) \
    asm("mov.b64 %0, {%1, %1};" : "=l"(out) : "f"(f))

#define UNPACK2(lo, hi, in) \
    asm("mov.b64 {%0, %1}, %2;" : "=f"(lo), "=f"(hi) : "l"(in))

// ---------------------------------------------------------------------------
// Kernel 1: per-position e = va . tanh(Wa q + Ua k + b), w = mask ? exp(e) : 0
// Tile: 64 positions x 64 out-dims. 128 threads, each 8 pos x 4 dims.
// Two K-phases (q*Wa then k*Ua) to halve smem -> 6 CTAs/SM.
// Math uses packed fma.rn.f32x2 (pairs along positions).
// ---------------------------------------------------------------------------
__global__ __launch_bounds__(128) void attn_logits_kernel(
    const float* __restrict__ q, const float* __restrict__ k,
    const int* __restrict__ mask,
    const float* __restrict__ Wa_w, const float* __restrict__ Wa_b,
    const float* __restrict__ Ua_w, const float* __restrict__ Ua_b,
    const float* __restrict__ va_w, const float* __restrict__ va_b)
{
    extern __shared__ float sm[];
    float* Ws   = sm;                      // [KH][WST]  weights, Ws[kk][d]
    float* Xs   = Ws + KH * WST;           // [KH][TS]   inputs,  Xs[kk][pos]
    float* bias = Xs + KH * TS;            // [64]
    float* vas  = bias + DD;               // [64]

    const int t = threadIdx.x;             // 0..127
    const int pos0 = blockIdx.x * TS;      // global flat position base

    if (t < 64) {
        bias[t] = Wa_b[t] + Ua_b[t];
        vas[t]  = va_w[t];
    }

    const int tx = t & 15;   // dim group: dims 4*tx .. 4*tx+3
    const int ty = t >> 4;   // pos group: pos  8*ty .. 8*ty+7

    // acc2[pp][d]: packed (pos 2*pp, pos 2*pp+1) for dim 4*tx+d
    unsigned long long acc2[4][4];
    #pragma unroll
    for (int i = 0; i < 4; i++)
        #pragma unroll
        for (int j = 0; j < 4; j++) acc2[i][j] = 0ull;

    const int d_ld  = t & 63;              // weight-load: output dim
    const int sub   = t >> 6;              // k-subrange half (0/1)
    const int p_ld  = t & 63;              // x-load: position

    #pragma unroll 1
    for (int ph = 0; ph < 2; ph++) {
        const float* W = ph ? Ua_w : Wa_w;
        const float* X = ph ? k : q;

        if (ph) __syncthreads();           // prior compute done before overwrite

        // weights transposed: Ws[kk][d] = W[d][kk], kk in [32*sub, 32*sub+32)
        {
            const float4* w4 = (const float4*)(W + d_ld * DD + 32 * sub);
            #pragma unroll
            for (int i = 0; i < 8; i++) {
                float4 a = w4[i];
                int kk = 32 * sub + 4 * i;
                Ws[(kk + 0) * WST + d_ld] = a.x;
                Ws[(kk + 1) * WST + d_ld] = a.y;
                Ws[(kk + 2) * WST + d_ld] = a.z;
                Ws[(kk + 3) * WST + d_ld] = a.w;
            }
        }
        // x transposed: Xs[kk][p] = X[pos0+p][kk]
        {
            const float4* x4 = (const float4*)(X + (size_t)(pos0 + p_ld) * DD + 32 * sub);
            #pragma unroll
            for (int i = 0; i < 8; i++) {
                float4 a = x4[i];
                int kk = 32 * sub + 4 * i;
                Xs[(kk + 0) * TS + p_ld] = a.x;
                Xs[(kk + 1) * TS + p_ld] = a.y;
                Xs[(kk + 2) * TS + p_ld] = a.z;
                Xs[(kk + 3) * TS + p_ld] = a.w;
            }
        }
        __syncthreads();

        #pragma unroll 8
        for (int kk = 0; kk < KH; kk++) {
            float4 w = *(const float4*)&Ws[kk * WST + 4 * tx];
            // positions come pre-packed as f32 pairs from contiguous smem
            ulonglong2 xa = *(const ulonglong2*)&Xs[kk * TS + 8 * ty];
            ulonglong2 xb = *(const ulonglong2*)&Xs[kk * TS + 8 * ty + 4];
            unsigned long long xp[4] = {xa.x, xa.y, xb.x, xb.y};
            unsigned long long w2[4];
            PACK_BCAST(w2[0], w.x);
            PACK_BCAST(w2[1], w.y);
            PACK_BCAST(w2[2], w.z);
            PACK_BCAST(w2[3], w.w);
            #pragma unroll
            for (int pp = 0; pp < 4; pp++) {
                FMA_F32X2(acc2[pp][0], xp[pp], w2[0]);
                FMA_F32X2(acc2[pp][1], xp[pp], w2[1]);
                FMA_F32X2(acc2[pp][2], xp[pp], w2[2]);
                FMA_F32X2(acc2[pp][3], xp[pp], w2[3]);
            }
        }
    }

    // ---- epilogue: tanh, va-dot, 16-lane reduce, masked exp ----
    float b0 = bias[4 * tx + 0], b1 = bias[4 * tx + 1];
    float b2 = bias[4 * tx + 2], b3 = bias[4 * tx + 3];
    float v0 = vas[4 * tx + 0], v1 = vas[4 * tx + 1];
    float v2 = vas[4 * tx + 2], v3 = vas[4 * tx + 3];
    float vb = va_b[0];

    float ep[8];
    #pragma unroll
    for (int pp = 0; pp < 4; pp++) {
        float a0[4], a1[4];
        UNPACK2(a0[0], a1[0], acc2[pp][0]);
        UNPACK2(a0[1], a1[1], acc2[pp][1]);
        UNPACK2(a0[2], a1[2], acc2[pp][2]);
        UNPACK2(a0[3], a1[3], acc2[pp][3]);
        float s0, s1;
        s0  = v0 * tanh_fast(a0[0] + b0);
        s0 += v1 * tanh_fast(a0[1] + b1);
        s0 += v2 * tanh_fast(a0[2] + b2);
        s0 += v3 * tanh_fast(a0[3] + b3);
        s1  = v0 * tanh_fast(a1[0] + b0);
        s1 += v1 * tanh_fast(a1[1] + b1);
        s1 += v2 * tanh_fast(a1[2] + b2);
        s1 += v3 * tanh_fast(a1[3] + b3);
        #pragma unroll
        for (int m = 8; m >= 1; m >>= 1) {
            s0 += __shfl_xor_sync(0xffffffffu, s0, m, 16);
            s1 += __shfl_xor_sync(0xffffffffu, s1, m, 16);
        }
        ep[2 * pp] = s0;
        ep[2 * pp + 1] = s1;
    }

    if (tx == 0) {
        #pragma unroll
        for (int i = 0; i < 8; i++) {
            int pos = pos0 + 8 * ty + i;
            float e = ep[i] + vb;
            float w = (mask[pos] != 0) ? __expf(e) : 0.f;
            g_w[pos] = w;
        }
    }
}

// ---------------------------------------------------------------------------
// Kernel 2: per-(b,h) sum of w over L, store reciprocal. Deterministic.
// ---------------------------------------------------------------------------
__global__ __launch_bounds__(256) void row_sum_kernel()
{
    __shared__ float red[256];
    int bh = blockIdx.x;
    int t = threadIdx.x;
    float s = 0.f;
    const float4* wrow = (const float4*)(g_w + (size_t)bh * LL);
    for (int l = t; l < LL / 4; l += 256) {
        float4 w4 = wrow[l];
        s += (w4.x + w4.y) + (w4.z + w4.w);
    }
    red[t] = s;
    __syncthreads();
    for (int m = 128; m > 0; m >>= 1) {
        if (t < m) red[t] += red[t + m];
        __syncthreads();
    }
    if (t == 0) g_rsum[bh] = 1.f / red[0];
}

// ---------------------------------------------------------------------------
// Kernel 3: out = alpha * v  (float4)
// ---------------------------------------------------------------------------
__global__ __launch_bounds__(1024) void scale_v_kernel(
    const float* __restrict__ v, float* __restrict__ out)
{
    int i4 = blockIdx.x * 1024 + threadIdx.x;   // 8192 blocks * 1024 = N/4 exactly
    int pos = i4 >> 4;                           // 16 float4 per position
    int bh  = pos >> 13;                         // / 8192
    float w = g_w[pos] * g_rsum[bh];
    float4 vv = ((const float4*)v)[i4];
    vv.x *= w; vv.y *= w; vv.z *= w; vv.w *= w;
    ((float4*)out)[i4] = vv;
}

extern "C" void kernel_launch(void* const* d_in, const int* in_sizes, int n_in,
                              void* d_out, int out_size)
{
    const float* q    = (const float*)d_in[0];
    const float* k    = (const float*)d_in[1];
    const float* v    = (const float*)d_in[2];
    const int*   mask = (const int*)d_in[3];
    const float* Wa_w = (const float*)d_in[4];
    const float* Wa_b = (const float*)d_in[5];
    const float* Ua_w = (const float*)d_in[6];
    const float* Ua_b = (const float*)d_in[7];
    const float* va_w = (const float*)d_in[8];
    const float* va_b = (const float*)d_in[9];
    float* out = (float*)d_out;

    const int smem1 = (KH * WST + KH * TS + 2 * DD) * (int)sizeof(float); // 34304 B
    cudaFuncSetAttribute(attn_logits_kernel,
                         cudaFuncAttributeMaxDynamicSharedMemorySize, smem1);

    attn_logits_kernel<<<NPOS / TS, 128, smem1>>>(q, k, mask, Wa_w, Wa_b,
                                                  Ua_w, Ua_b, va_w, va_b);
    row_sum_kernel<<<BH, 256>>>();
    scale_v_kernel<<<(NPOS * DD / 4) / 1024, 1024>>>(v, out);
}